// round 10
// baseline (speedup 1.0000x reference)
#include <cuda_runtime.h>
#include <cuda_bf16.h>
#include <cstdint>

// B=512, H=8, C=8192.
//   loss = -sum_{b,c} w'[c] * max(lg2(t ? p : 1-p), -100/ln2)
//   w'[c] = (ln2/C) * sum_h lam[h]*La[h,c]
// Kernel A (PDL-overlapped): computes w into g_w4, zeroes out.
// Kernel B: cp.async (LDGSTS) deep-queue streaming into 64KB smem to escape
// the per-SM outstanding-LDG cap (~64 LDG.128 in flight = ~4.5 TB/s ceiling
// observed R1-R8 on the register-return path). Each thread stages its 16
// float4s in smem and reads back ONLY its own writes (no syncthreads).

#define B_DIM 512
#define H_DIM 8
#define C_DIM 8192
#define N4 (B_DIM * C_DIM / 4)        // 1048576 float4 pairs
#define C4 (C_DIM / 4)                // 2048
#define NT 131072                     // total threads in kernel B
#define NBLOCKS (NT / 256)            // 512
#define PAIRS 8                       // float4-pairs per thread
#define SMEM_BYTES (256 * 2 * PAIRS * 16)   // 65536

#define LOG2_CLAMP (-144.26950408889634f)   // -100 / ln2
#define LN2 (0.6931471805599453f)

__device__ float g_w4[C_DIM];         // per-class weight * ln2 / C

// ---------------------------------------------------------------------------
// Kernel A: trigger B immediately, then compute w and zero the output.
// ---------------------------------------------------------------------------
__global__ void multibce_weights_kernel(const float* __restrict__ La,
                                        const float* __restrict__ lam,
                                        float* __restrict__ out) {
    cudaTriggerProgrammaticLaunchCompletion();
    int c = blockIdx.x * blockDim.x + threadIdx.x;
    if (c < C_DIM) {
        float s = 0.0f;
#pragma unroll
        for (int h = 0; h < H_DIM; ++h) {
            s = fmaf(lam[h], La[h * C_DIM + c], s);
        }
        g_w4[c] = s * (LN2 / (float)C_DIM);
    }
    if (c == 0) out[0] = 0.0f;
}

// ---------------------------------------------------------------------------
// Kernel B
// ---------------------------------------------------------------------------
__device__ __forceinline__ float term1(float p, float t) {
    // x = t ? p : 1-p  (exact for binary t)
    float x = fmaf(p, 2.0f * t - 1.0f, 1.0f - t);
    return fmaxf(__log2f(x), LOG2_CLAMP);
}

__device__ __forceinline__ void cp16(unsigned s, const void* g) {
    asm volatile("cp.async.cg.shared.global [%0], [%1], 16;\n"
                 :: "r"(s), "l"(g));
}

__global__ void __launch_bounds__(256, 3)
multibce_reduce_kernel(const float4* __restrict__ yp,
                       const float4* __restrict__ yt,
                       float* __restrict__ out) {
    extern __shared__ float4 buf[];   // [2*PAIRS][256] float4
    const int tx  = threadIdx.x;
    const int tid = blockIdx.x * 256 + tx;

    const unsigned sbase = (unsigned)__cvta_generic_to_shared(buf);

    // Issue all 16 async copies (deep queue, no register writeback).
#pragma unroll
    for (int j = 0; j < PAIRS; ++j) {
        cp16(sbase + (unsigned)((j * 256 + tx) * 16),           &yp[tid + j * NT]);
        cp16(sbase + (unsigned)(((PAIRS + j) * 256 + tx) * 16), &yt[tid + j * NT]);
    }
    asm volatile("cp.async.commit_group;\n");
    asm volatile("cp.async.wait_group 0;\n" ::: "memory");

    // Compute raw (w-free) per-component sums from own smem slots.
    float sx = 0.0f, sy = 0.0f, sz = 0.0f, sw = 0.0f;
#pragma unroll
    for (int j = 0; j < PAIRS; ++j) {
        float4 p = buf[j * 256 + tx];
        float4 t = buf[(PAIRS + j) * 256 + tx];
        sx += term1(p.x, t.x);
        sy += term1(p.y, t.y);
        sz += term1(p.z, t.z);
        sw += term1(p.w, t.w);
    }

    // Wait for kernel A, then apply weights.
    cudaGridDependencySynchronize();
    float4 w = reinterpret_cast<const float4*>(g_w4)[tid & (C4 - 1)];
    float acc = fmaf(w.x, sx, fmaf(w.y, sy, fmaf(w.z, sz, w.w * sw)));

    // warp reduce
#pragma unroll
    for (int o = 16; o > 0; o >>= 1)
        acc += __shfl_xor_sync(0xFFFFFFFFu, acc, o);

    // block reduce
    __shared__ float smem[8];
    int lane = tx & 31;
    int warp = tx >> 5;
    if (lane == 0) smem[warp] = acc;
    __syncthreads();
    if (warp == 0) {
        acc = (lane < 8) ? smem[lane] : 0.0f;
#pragma unroll
        for (int o = 4; o > 0; o >>= 1)
            acc += __shfl_xor_sync(0xFFFFFFFFu, acc, o);
        if (lane == 0) atomicAdd(out, -acc);   // loss = -sum
    }
}

// ---------------------------------------------------------------------------
extern "C" void kernel_launch(void* const* d_in, const int* in_sizes, int n_in,
                              void* d_out, int out_size) {
    const float* y_pred = (const float*)d_in[0];
    const float* y_true = (const float*)d_in[1];
    const float* La     = (const float*)d_in[2];
    const float* lam    = (const float*)d_in[3];
    float* out = (float*)d_out;

    // Opt-in to >48KB dynamic smem (config call, not captured, idempotent).
    cudaFuncSetAttribute(multibce_reduce_kernel,
                         cudaFuncAttributeMaxDynamicSharedMemorySize,
                         SMEM_BYTES);

    multibce_weights_kernel<<<(C_DIM + 255) / 256, 256>>>(La, lam, out);

    cudaLaunchConfig_t cfg = {};
    cfg.gridDim  = dim3(NBLOCKS);
    cfg.blockDim = dim3(256);
    cfg.dynamicSmemBytes = SMEM_BYTES;
    cfg.stream = 0;
    cudaLaunchAttribute attr[1];
    attr[0].id = cudaLaunchAttributeProgrammaticStreamSerialization;
    attr[0].val.programmaticStreamSerializationAllowed = 1;
    cfg.attrs = attr;
    cfg.numAttrs = 1;
    cudaLaunchKernelEx(&cfg, multibce_reduce_kernel,
                       (const float4*)y_pred, (const float4*)y_true, out);
}

// round 11
// speedup vs baseline: 1.1516x; 1.1516x over previous
#include <cuda_runtime.h>
#include <cuda_bf16.h>
#include <cstdint>

// B=512, H=8, C=8192.
//   loss = -sum_{b,c} w'[c] * max(lg2(t ? p : 1-p), -100/ln2)
//   w'[c] = (ln2/C) * sum_h lam[h]*La[h,c]
// Kernel A (PDL-overlapped): computes w into g_w4, zeroes out.
// Kernel B (R8 structure): 512 blocks x 256 thr, 2 chunks x 4 float4-pairs,
// front-batched LDG.128, deferred-w, one atomicAdd per block.
// NEW: fire-and-forget prefetch.global.L2 of chunk-1 addresses before chunk-0
// loads — fills the DRAM queue beyond the LDG scoreboard so chunk-1's DRAM
// time overlaps chunk-0's load+compute, and chunk-1 LDGs land as L2 hits.

#define B_DIM 512
#define H_DIM 8
#define C_DIM 8192
#define N4 (B_DIM * C_DIM / 4)        // 1048576 float4 pairs
#define C4 (C_DIM / 4)                // 2048
#define NT 131072                     // total threads in kernel B
#define NBLOCKS (NT / 256)            // 512
#define PAIRS 8                       // float4-pairs per thread

#define LOG2_CLAMP (-144.26950408889634f)   // -100 / ln2
#define LN2 (0.6931471805599453f)

__device__ float g_w4[C_DIM];         // per-class weight * ln2 / C

// ---------------------------------------------------------------------------
// Kernel A: trigger B immediately, then compute w and zero the output.
// ---------------------------------------------------------------------------
__global__ void multibce_weights_kernel(const float* __restrict__ La,
                                        const float* __restrict__ lam,
                                        float* __restrict__ out) {
    cudaTriggerProgrammaticLaunchCompletion();
    int c = blockIdx.x * blockDim.x + threadIdx.x;
    if (c < C_DIM) {
        float s = 0.0f;
#pragma unroll
        for (int h = 0; h < H_DIM; ++h) {
            s = fmaf(lam[h], La[h * C_DIM + c], s);
        }
        g_w4[c] = s * (LN2 / (float)C_DIM);
    }
    if (c == 0) out[0] = 0.0f;
}

// ---------------------------------------------------------------------------
// Kernel B
// ---------------------------------------------------------------------------
__device__ __forceinline__ float term1(float p, float t) {
    // x = t ? p : 1-p  (exact for binary t)
    float x = fmaf(p, 2.0f * t - 1.0f, 1.0f - t);
    return fmaxf(__log2f(x), LOG2_CLAMP);
}

__device__ __forceinline__ void l2_prefetch(const void* g) {
    asm volatile("prefetch.global.L2 [%0];" :: "l"(g));
}

__global__ void __launch_bounds__(256, 4)
multibce_reduce_kernel(const float4* __restrict__ yp,
                       const float4* __restrict__ yt,
                       float* __restrict__ out) {
    const int tid = blockIdx.x * 256 + threadIdx.x;

    // Fire-and-forget: queue chunk-1's DRAM traffic immediately (no scoreboard).
#pragma unroll
    for (int j = 4; j < 8; ++j) {
        l2_prefetch(&yp[tid + j * NT]);
        l2_prefetch(&yt[tid + j * NT]);
    }

    float sx = 0.0f, sy = 0.0f, sz = 0.0f, sw = 0.0f;

#pragma unroll 1
    for (int jc = 0; jc < 2; ++jc) {
        int base = tid + jc * 4 * NT;
        float4 p0 = yp[base];
        float4 p1 = yp[base + NT];
        float4 p2 = yp[base + 2 * NT];
        float4 p3 = yp[base + 3 * NT];
        float4 t0 = yt[base];
        float4 t1 = yt[base + NT];
        float4 t2 = yt[base + 2 * NT];
        float4 t3 = yt[base + 3 * NT];

        sx += term1(p0.x, t0.x) + term1(p1.x, t1.x)
            + term1(p2.x, t2.x) + term1(p3.x, t3.x);
        sy += term1(p0.y, t0.y) + term1(p1.y, t1.y)
            + term1(p2.y, t2.y) + term1(p3.y, t3.y);
        sz += term1(p0.z, t0.z) + term1(p1.z, t1.z)
            + term1(p2.z, t2.z) + term1(p3.z, t3.z);
        sw += term1(p0.w, t0.w) + term1(p1.w, t1.w)
            + term1(p2.w, t2.w) + term1(p3.w, t3.w);
    }

    // Wait for kernel A, then apply weights.
    cudaGridDependencySynchronize();
    float4 w = reinterpret_cast<const float4*>(g_w4)[tid & (C4 - 1)];
    float acc = fmaf(w.x, sx, fmaf(w.y, sy, fmaf(w.z, sz, w.w * sw)));

    // warp reduce
#pragma unroll
    for (int o = 16; o > 0; o >>= 1)
        acc += __shfl_xor_sync(0xFFFFFFFFu, acc, o);

    // block reduce
    __shared__ float smem[8];
    int lane = threadIdx.x & 31;
    int warp = threadIdx.x >> 5;
    if (lane == 0) smem[warp] = acc;
    __syncthreads();
    if (warp == 0) {
        acc = (lane < 8) ? smem[lane] : 0.0f;
#pragma unroll
        for (int o = 4; o > 0; o >>= 1)
            acc += __shfl_xor_sync(0xFFFFFFFFu, acc, o);
        if (lane == 0) atomicAdd(out, -acc);   // loss = -sum
    }
}

// ---------------------------------------------------------------------------
extern "C" void kernel_launch(void* const* d_in, const int* in_sizes, int n_in,
                              void* d_out, int out_size) {
    const float* y_pred = (const float*)d_in[0];
    const float* y_true = (const float*)d_in[1];
    const float* La     = (const float*)d_in[2];
    const float* lam    = (const float*)d_in[3];
    float* out = (float*)d_out;

    multibce_weights_kernel<<<(C_DIM + 255) / 256, 256>>>(La, lam, out);

    cudaLaunchConfig_t cfg = {};
    cfg.gridDim  = dim3(NBLOCKS);
    cfg.blockDim = dim3(256);
    cfg.dynamicSmemBytes = 0;
    cfg.stream = 0;
    cudaLaunchAttribute attr[1];
    attr[0].id = cudaLaunchAttributeProgrammaticStreamSerialization;
    attr[0].val.programmaticStreamSerializationAllowed = 1;
    cfg.attrs = attr;
    cfg.numAttrs = 1;
    cudaLaunchKernelEx(&cfg, multibce_reduce_kernel,
                       (const float4*)y_pred, (const float4*)y_true, out);
}

// round 12
// speedup vs baseline: 1.2461x; 1.0820x over previous
#include <cuda_runtime.h>
#include <cuda_bf16.h>
#include <cstdint>

// B=512, H=8, C=8192.
//   loss = -sum_{b,c} w'[c] * max(lg2(t ? p : 1-p), -100/ln2)
//   w'[c] = (ln2/C) * sum_h lam[h]*La[h,c]
// Kernel A (PDL-overlapped): computes w into g_w4, zeroes out.
// Kernel B (R8 structure, prefetch removed): 512 blocks x 256 thr, 2 chunks x
// 4 float4-pairs, front-batched LDG.128, deferred-w.
// NEW: log batching. All 8 j-samples of a component share one weight, so
//   sum_j lg2(x_j) = lg2(prod of 4) + lg2(prod of 4)  -> 8 MUFU/thread vs 32.
// x==0 (p==0&t==1 or p-rounding) handled by rare-path guard: substitute 1.0
// and count a -144.27 penalty => identical clamp semantics to torch BCE.

#define B_DIM 512
#define H_DIM 8
#define C_DIM 8192
#define C4 (C_DIM / 4)                // 2048
#define NT 131072                     // total threads in kernel B
#define NBLOCKS (NT / 256)            // 512
#define PAIRS 8

#define LOG2_CLAMP (-144.26950408889634f)   // -100 / ln2
#define LN2 (0.6931471805599453f)

__device__ float g_w4[C_DIM];         // per-class weight * ln2 / C

// ---------------------------------------------------------------------------
// Kernel A: trigger B immediately, then compute w and zero the output.
// ---------------------------------------------------------------------------
__global__ void multibce_weights_kernel(const float* __restrict__ La,
                                        const float* __restrict__ lam,
                                        float* __restrict__ out) {
    cudaTriggerProgrammaticLaunchCompletion();
    int c = blockIdx.x * blockDim.x + threadIdx.x;
    if (c < C_DIM) {
        float s = 0.0f;
#pragma unroll
        for (int h = 0; h < H_DIM; ++h) {
            s = fmaf(lam[h], La[h * C_DIM + c], s);
        }
        g_w4[c] = s * (LN2 / (float)C_DIM);
    }
    if (c == 0) out[0] = 0.0f;
}

// ---------------------------------------------------------------------------
// Kernel B
// ---------------------------------------------------------------------------
// x = t ? p : 1-p (exact for binary t). Nonzero x >= ~6e-8, so only exact
// zeros need the clamp; substitute 1.0 and count the -144.27 penalty.
__device__ __forceinline__ float xval(float p, float t, float& pen) {
    float x = fmaf(p, 2.0f * t - 1.0f, 1.0f - t);
    if (x < 1e-40f) { pen += 1.0f; x = 1.0f; }
    return x;
}

__global__ void __launch_bounds__(256, 4)
multibce_reduce_kernel(const float4* __restrict__ yp,
                       const float4* __restrict__ yt,
                       float* __restrict__ out) {
    const int tid = blockIdx.x * 256 + threadIdx.x;

    float sx = 0.0f, sy = 0.0f, sz = 0.0f, sw = 0.0f;
    float px = 0.0f, py = 0.0f, pz = 0.0f, pw = 0.0f;   // zero-penalty counts

#pragma unroll 1
    for (int jc = 0; jc < 2; ++jc) {
        int base = tid + jc * 4 * NT;
        float4 p0 = yp[base];
        float4 p1 = yp[base + NT];
        float4 p2 = yp[base + 2 * NT];
        float4 p3 = yp[base + 3 * NT];
        float4 t0 = yt[base];
        float4 t1 = yt[base + NT];
        float4 t2 = yt[base + 2 * NT];
        float4 t3 = yt[base + 3 * NT];

        float mx = xval(p0.x, t0.x, px) * xval(p1.x, t1.x, px)
                 * xval(p2.x, t2.x, px) * xval(p3.x, t3.x, px);
        float my = xval(p0.y, t0.y, py) * xval(p1.y, t1.y, py)
                 * xval(p2.y, t2.y, py) * xval(p3.y, t3.y, py);
        float mz = xval(p0.z, t0.z, pz) * xval(p1.z, t1.z, pz)
                 * xval(p2.z, t2.z, pz) * xval(p3.z, t3.z, pz);
        float mw = xval(p0.w, t0.w, pw) * xval(p1.w, t1.w, pw)
                 * xval(p2.w, t2.w, pw) * xval(p3.w, t3.w, pw);

        sx += __log2f(mx);
        sy += __log2f(my);
        sz += __log2f(mz);
        sw += __log2f(mw);
    }

    // Fold zero penalties (exact clamp contribution per zero element).
    sx = fmaf(px, LOG2_CLAMP, sx);
    sy = fmaf(py, LOG2_CLAMP, sy);
    sz = fmaf(pz, LOG2_CLAMP, sz);
    sw = fmaf(pw, LOG2_CLAMP, sw);

    // Wait for kernel A, then apply weights.
    cudaGridDependencySynchronize();
    float4 w = reinterpret_cast<const float4*>(g_w4)[tid & (C4 - 1)];
    float acc = fmaf(w.x, sx, fmaf(w.y, sy, fmaf(w.z, sz, w.w * sw)));

    // warp reduce
#pragma unroll
    for (int o = 16; o > 0; o >>= 1)
        acc += __shfl_xor_sync(0xFFFFFFFFu, acc, o);

    // block reduce
    __shared__ float smem[8];
    int lane = threadIdx.x & 31;
    int warp = threadIdx.x >> 5;
    if (lane == 0) smem[warp] = acc;
    __syncthreads();
    if (warp == 0) {
        acc = (lane < 8) ? smem[lane] : 0.0f;
#pragma unroll
        for (int o = 4; o > 0; o >>= 1)
            acc += __shfl_xor_sync(0xFFFFFFFFu, acc, o);
        if (lane == 0) atomicAdd(out, -acc);   // loss = -sum
    }
}

// ---------------------------------------------------------------------------
extern "C" void kernel_launch(void* const* d_in, const int* in_sizes, int n_in,
                              void* d_out, int out_size) {
    const float* y_pred = (const float*)d_in[0];
    const float* y_true = (const float*)d_in[1];
    const float* La     = (const float*)d_in[2];
    const float* lam    = (const float*)d_in[3];
    float* out = (float*)d_out;

    multibce_weights_kernel<<<(C_DIM + 255) / 256, 256>>>(La, lam, out);

    cudaLaunchConfig_t cfg = {};
    cfg.gridDim  = dim3(NBLOCKS);
    cfg.blockDim = dim3(256);
    cfg.dynamicSmemBytes = 0;
    cfg.stream = 0;
    cudaLaunchAttribute attr[1];
    attr[0].id = cudaLaunchAttributeProgrammaticStreamSerialization;
    attr[0].val.programmaticStreamSerializationAllowed = 1;
    cfg.attrs = attr;
    cfg.numAttrs = 1;
    cudaLaunchKernelEx(&cfg, multibce_reduce_kernel,
                       (const float4*)y_pred, (const float4*)y_true, out);
}